// round 6
// baseline (speedup 1.0000x reference)
#include <cuda_runtime.h>

// MS-SSIM loss, 4 scales. v6: single persistent-scheduler kernel.
// All 16320 tiles (4 scales x 48 planes) ordered by a global ticket counter;
// cross-scale deps enforced by per-plane done counters (acquire/release),
// so scale s of plane p pipelines with scale s-1 of planes p+1.. .
// Tile math: v5's f32x2 sum/diff form (s=a+b, d=a-b; conv (s,d),(s^2,d^2)).

#define NPLANES 48
typedef unsigned long long ull;

// tickets: scale-major, plane-major within scale
#define S0_TILES 12288   // 16x16 x 48
#define S1_TILES 3072    // 8x8 x 48
#define S2_TILES 768     // 4x4 x 48
#define S3_TILES 192     // 2x2 x 48
#define TOT_TILES (S0_TILES + S1_TILES + S2_TILES + S3_TILES)  // 16320

// ---- device globals (no allocations allowed) ----
__device__ float  g_acc[4];
__device__ int    g_ticket;
__device__ int    g_pdone[3][NPLANES];   // completed tiles per (scale, plane)
__device__ float2 g_p1[48 * 256 * 256];
__device__ float2 g_p2[48 * 128 * 128];
__device__ float2 g_p3[48 * 64 * 64];

// ---- packed f32x2 helpers ----
__device__ __forceinline__ ull pack2(float lo, float hi) {
    ull r;
    asm("mov.b64 %0, {%1, %2};" : "=l"(r) : "f"(lo), "f"(hi));
    return r;
}
__device__ __forceinline__ void unpack2(ull v, float& lo, float& hi) {
    asm("mov.b64 {%0, %1}, %2;" : "=f"(lo), "=f"(hi) : "l"(v));
}
__device__ __forceinline__ void ffma2(ull& acc, ull a, ull b) {
    asm("fma.rn.f32x2 %0, %1, %2, %0;" : "+l"(acc) : "l"(a), "l"(b));
}
__device__ __forceinline__ ull fmul2(ull a, ull b) {
    ull d;
    asm("mul.rn.f32x2 %0, %1, %2;" : "=l"(d) : "l"(a), "l"(b));
    return d;
}
__device__ __forceinline__ int ld_acquire(const int* p) {
    int v;
    asm volatile("ld.acquire.gpu.global.b32 %0, [%1];" : "=r"(v) : "l"(p) : "memory");
    return v;
}

// Gaussian(11, sigma=1.5), normalized.
#define G_LIST { \
    0.00102838f, 0.00759875f, 0.03600077f, 0.10936070f, 0.21300553f, \
    0.26601172f, \
    0.21300553f, 0.10936070f, 0.03600077f, 0.00759875f, 0.00102838f }

// Fixed tile config: 32x32 outputs, 256 threads, 4 rows/thread in V-pass.
#define TW 32
#define TH 32
#define RPT 4
#define NT 256
#define IH 42          // TH + 10
#define LP 48          // sSD row width in (s,d) pixels (loads start at tx-8)
#define LW4 12         // float4 slots per row, scale-0 path
#define NF4 24         // float4 loads per row, pooled path (2 px each)
#define SLOTS 8        // 4-wide output groups per row
#define HP 32          // hbuf pitch (rows are 256B, conflict-free)

__global__ void __launch_bounds__(NT)
ssim_persistent(const float* __restrict__ A0, const float* __restrict__ B0)
{
    __shared__ __align__(16) float2 sSD[IH][LP];
    __shared__ __align__(16) ull h1[IH][HP];
    __shared__ __align__(16) ull h2[IH][HP];
    __shared__ float red[NT / 32];
    __shared__ int s_ticket;

    const float G[11] = G_LIST;
    ull g2[11];
    #pragma unroll
    for (int k = 0; k < 11; k++) g2[k] = pack2(G[k], G[k]);

    const int tid = threadIdx.x;

    for (;;) {
        if (tid == 0) s_ticket = atomicAdd(&g_ticket, 1);
        __syncthreads();
        const int t = s_ticket;
        if (t >= TOT_TILES) return;

        // ---- decode ticket -> (scale, plane, tile x/y) ----
        int scale, plane, txi, tyi;
        if (t < S0_TILES) {
            scale = 0; plane = t >> 8; int rem = t & 255; tyi = rem >> 4; txi = rem & 15;
        } else if (t < S0_TILES + S1_TILES) {
            int r = t - S0_TILES;
            scale = 1; plane = r >> 6; int rem = r & 63; tyi = rem >> 3; txi = rem & 7;
        } else if (t < S0_TILES + S1_TILES + S2_TILES) {
            int r = t - (S0_TILES + S1_TILES);
            scale = 2; plane = r >> 4; int rem = r & 15; tyi = rem >> 2; txi = rem & 3;
        } else {
            int r = t - (S0_TILES + S1_TILES + S2_TILES);
            scale = 3; plane = r >> 2; int rem = r & 3; tyi = rem >> 1; txi = rem & 1;
        }
        const int W = 512 >> scale;
        const int H = W;
        const int tx = txi * TW;
        const int ty = tyi * TH;
        const size_t pbase = (size_t)plane * (size_t)W * (size_t)H;

        // ---- wait for producing scale (whole plane done) ----
        if (scale > 0 && tid == 0) {
            const int tpp = (scale == 1) ? 256 : (scale == 2) ? 64 : 16;
            const int* cnt = &g_pdone[scale - 1][plane];
            int ns = 64;
            while (ld_acquire(cnt) < tpp) {
                __nanosleep(ns);
                if (ns < 2048) ns <<= 1;
            }
        }
        __syncthreads();

        // ---- stage 1: load tile + halo as interleaved (s,d) ----
        if (scale == 0) {
            for (int i = tid; i < IH * LW4; i += NT) {
                int r = i / LW4;
                int s = i - r * LW4;
                int gy = ty + r - 5;
                int gx = tx + 4 * s - 8;
                float4 a = make_float4(0.f, 0.f, 0.f, 0.f);
                float4 b = a;
                if ((unsigned)gy < (unsigned)H && (unsigned)gx <= (unsigned)(W - 4)) {
                    size_t idx = pbase + (size_t)gy * W + gx;
                    a = *reinterpret_cast<const float4*>(A0 + idx);
                    b = *reinterpret_cast<const float4*>(B0 + idx);
                }
                float4 lo = make_float4(a.x + b.x, a.x - b.x, a.y + b.y, a.y - b.y);
                float4 hi = make_float4(a.z + b.z, a.z - b.z, a.w + b.w, a.w - b.w);
                *reinterpret_cast<float4*>(&sSD[r][4 * s])     = lo;
                *reinterpret_cast<float4*>(&sSD[r][4 * s + 2]) = hi;
            }
        } else {
            const float2* P = (scale == 1) ? g_p1 : (scale == 2) ? g_p2 : g_p3;
            for (int i = tid; i < IH * NF4; i += NT) {
                int r = i / NF4;
                int s = i - r * NF4;
                int gy = ty + r - 5;
                int gx = tx + 2 * s - 8;
                float4 v = make_float4(0.f, 0.f, 0.f, 0.f);
                if ((unsigned)gy < (unsigned)H && (unsigned)gx <= (unsigned)(W - 2)) {
                    v = *reinterpret_cast<const float4*>(P + pbase + (size_t)gy * W + gx);
                }
                *reinterpret_cast<float4*>(&sSD[r][2 * s]) = v;
            }
        }
        __syncthreads();

        // ---- fused 2x2 avg-pool for the next scale ((s,d) is linear) ----
        if (scale < 3) {
            // PW*PH == 256 == NT: every thread writes one pooled pixel
            int pr = tid >> 4;       // /16
            int pc = tid & 15;
            int r = 5 + 2 * pr;
            int c = 8 + 2 * pc;
            float2 q00 = sSD[r][c],     q01 = sSD[r][c + 1];
            float2 q10 = sSD[r + 1][c], q11 = sSD[r + 1][c + 1];
            float2 o;
            o.x = 0.25f * (q00.x + q01.x + q10.x + q11.x);
            o.y = 0.25f * (q00.y + q01.y + q10.y + q11.y);
            int pW = W >> 1;
            size_t pidx = (size_t)plane * pW * pW
                        + (size_t)((ty >> 1) + pr) * pW + ((tx >> 1) + pc);
            float2* PD = (scale == 0) ? g_p1 : (scale == 1) ? g_p2 : g_p3;
            PD[pidx] = o;
        }

        // ---- stage 2: horizontal 11-tap pass, 4 outputs/thread, f32x2 ----
        for (int i = tid; i < IH * SLOTS; i += NT) {
            int r  = i / SLOTS;
            int sl = i - r * SLOTS;
            int c0 = 4 * sl;
            ull w[20];
            #pragma unroll
            for (int q = 0; q < 10; q++) {
                ulonglong2 u = *reinterpret_cast<const ulonglong2*>(&sSD[r][c0 + 2 * q]);
                w[2 * q]     = u.x;
                w[2 * q + 1] = u.y;
            }
            ull a1[4], a2[4];
            #pragma unroll
            for (int j = 0; j < 4; j++) { a1[j] = 0ull; a2[j] = 0ull; }
            #pragma unroll
            for (int tt = 0; tt < 14; tt++) {
                ull v  = w[tt + 3];
                ull v2 = fmul2(v, v);
                #pragma unroll
                for (int j = 0; j < 4; j++) {
                    int k = tt - j;
                    if (k >= 0 && k < 11) {
                        ffma2(a1[j], v,  g2[k]);
                        ffma2(a2[j], v2, g2[k]);
                    }
                }
            }
            *reinterpret_cast<ulonglong2*>(&h1[r][c0])     = make_ulonglong2(a1[0], a1[1]);
            *reinterpret_cast<ulonglong2*>(&h1[r][c0 + 2]) = make_ulonglong2(a1[2], a1[3]);
            *reinterpret_cast<ulonglong2*>(&h2[r][c0])     = make_ulonglong2(a2[0], a2[1]);
            *reinterpret_cast<ulonglong2*>(&h2[r][c0 + 2]) = make_ulonglong2(a2[2], a2[3]);
        }
        __syncthreads();

        // ---- stage 3: vertical 11-tap pass (f32x2), SSIM map, reduce ----
        float acc = 0.0f;
        {
            const int c  = tid & (TW - 1);
            const int r0 = (tid >> 5) * RPT;
            ull s1[RPT], s2[RPT];
            #pragma unroll
            for (int j = 0; j < RPT; j++) { s1[j] = 0ull; s2[j] = 0ull; }
            #pragma unroll
            for (int tt = 0; tt < RPT + 10; tt++) {
                ull v1 = h1[r0 + tt][c];
                ull v2 = h2[r0 + tt][c];
                #pragma unroll
                for (int j = 0; j < RPT; j++) {
                    int k = tt - j;
                    if (k >= 0 && k < 11) {
                        ffma2(s1[j], v1, g2[k]);
                        ffma2(s2[j], v2, g2[k]);
                    }
                }
            }
            const float C1 = 1e-4f;
            const float C2 = 9e-4f;
            #pragma unroll
            for (int j = 0; j < RPT; j++) {
                float mus, mud, es2, ed2;
                unpack2(s1[j], mus, mud);
                unpack2(s2[j], es2, ed2);
                float Aq = mus * mus;
                float Bq = mud * mud;
                float mu12  = 0.25f * (Aq - Bq);
                float musq  = 0.5f  * (Aq + Bq);
                float sigs  = 0.5f  * (es2 + ed2) - musq;
                float sig12 = 0.25f * (es2 - ed2) - mu12;
                float num = (2.0f * mu12 + C1) * (2.0f * sig12 + C2);
                float den = (musq + C1) * (sigs + C2);
                acc += __fdividef(num, den);
            }
        }

        // ---- block reduce -> atomic, publish tile completion ----
        #pragma unroll
        for (int o = 16; o > 0; o >>= 1)
            acc += __shfl_down_sync(0xffffffffu, acc, o);
        if ((tid & 31) == 0) red[tid >> 5] = acc;
        __syncthreads();
        if (tid == 0) {
            float s = 0.f;
            #pragma unroll
            for (int w = 0; w < NT / 32; w++) s += red[w];
            atomicAdd(&g_acc[scale], s);
            if (scale < 3) {
                __threadfence();   // pool writes (pre-barrier) -> visible before count
                atomicAdd(&g_pdone[scale][plane], 1);
            }
        }
        // loop-top __syncthreads separates smem reuse across iterations
    }
}

__global__ void finalize_kernel(float* __restrict__ out) {
    const float w[4] = {0.0448f, 0.2856f, 0.3001f, 0.2363f};
    float loss = 0.0f;
    float cnt = 48.0f * 512.0f * 512.0f;
    #pragma unroll
    for (int s = 0; s < 4; s++) {
        loss += w[s] * (1.0f - g_acc[s] / cnt);
        cnt *= 0.25f;
    }
    out[0] = loss;
    // reset all scheduler state for the next (graph-replayed) run
    #pragma unroll
    for (int s = 0; s < 4; s++) g_acc[s] = 0.0f;
    for (int s = 0; s < 3; s++)
        for (int p = 0; p < NPLANES; p++) g_pdone[s][p] = 0;
    g_ticket = 0;
}

extern "C" void kernel_launch(void* const* d_in, const int* in_sizes, int n_in,
                              void* d_out, int out_size) {
    const float* img1 = (const float*)d_in[0];
    const float* img2 = (const float*)d_in[1];
    float* out = (float*)d_out;

    // persistent grid: 6 blocks/SM x 148 SMs (smem ~37.7KB -> 6 resident);
    // correctness does not depend on residency (queue-ordered claims).
    ssim_persistent<<<888, NT>>>(img1, img2);
    finalize_kernel<<<1, 1>>>(out);
}

// round 8
// speedup vs baseline: 1.1889x; 1.1889x over previous
#include <cuda_runtime.h>

// MS-SSIM loss, 4 scales. v7b: v7 with the pooled-path halo-load fix
// (NF4 = TW/2+8, was TW/2+4 -> right halo columns were stale garbage).
//   - 8-output H-pass groups (20B/out smem read)
//   - RPT=8 vertical pass (36B/out read)
//   - h1/h2 interleaved (LDS.128/STS.128)
//   - conflict-free pitches (sSD row=400B, h12 row=528B) + row-fastest stage2 map
// Math: f32x2 sum/diff form (s=a+b, d=a-b; conv (s,d) and (s^2,d^2)).

#define NPLANES 48
typedef unsigned long long ull;

// ---- device globals (no allocations allowed) ----
__device__ float  g_acc[4];            // zero-init at load; finalize resets
__device__ float2 g_p1[48 * 256 * 256];
__device__ float2 g_p2[48 * 128 * 128];
__device__ float2 g_p3[48 * 64 * 64];

// ---- packed f32x2 helpers ----
__device__ __forceinline__ ull pack2(float lo, float hi) {
    ull r;
    asm("mov.b64 %0, {%1, %2};" : "=l"(r) : "f"(lo), "f"(hi));
    return r;
}
__device__ __forceinline__ void unpack2(ull v, float& lo, float& hi) {
    asm("mov.b64 {%0, %1}, %2;" : "=f"(lo), "=f"(hi) : "l"(v));
}
__device__ __forceinline__ void ffma2(ull& acc, ull a, ull b) {
    asm("fma.rn.f32x2 %0, %1, %2, %0;" : "+l"(acc) : "l"(a), "l"(b));
}
__device__ __forceinline__ ull fmul2(ull a, ull b) {
    ull d;
    asm("mul.rn.f32x2 %0, %1, %2;" : "=l"(d) : "l"(a), "l"(b));
    return d;
}

// Gaussian(11, sigma=1.5), normalized.
#define G_LIST { \
    0.00102838f, 0.00759875f, 0.03600077f, 0.10936070f, 0.21300553f, \
    0.26601172f, \
    0.21300553f, 0.10936070f, 0.03600077f, 0.00759875f, 0.00102838f }

// TW: tile width, TH: tile height, RPT: rows/thread in V-pass.
template<int TW, int TH, int RPT>
__global__ void __launch_bounds__(TW * TH / RPT)
ssim_kernel(const float* __restrict__ A0, const float* __restrict__ B0,
            int scale, int W, int do_pool)
{
    constexpr int NT    = TW * TH / RPT;  // threads per block
    constexpr int IH    = TH + 10;        // rows incl. halo
    constexpr int LW4   = TW / 4 + 4;     // raw-float4 loads per row (scale 0)
    constexpr int NF4   = TW / 2 + 8;     // float4 (=2 px) loads per row (pooled) [FIX]
    constexpr int LP    = 4 * LW4 + 2;    // sSD pitch: 50/34 -> row 400/272B (quad-rotating)
    constexpr int SLOTS = TW / 8;         // 8-wide output groups per row
    constexpr int HP    = TW + 1;         // h12 pitch: 33/17 -> row 528/272B

    __shared__ __align__(16) float2 sSD[IH][LP];       // (s, d) per pixel
    __shared__ __align__(16) ulonglong2 h12[IH][HP];   // {conv(s,d), conv(s^2,d^2)}
    __shared__ float red[NT / 32];

    const float G[11] = G_LIST;
    ull g2[11];
    #pragma unroll
    for (int k = 0; k < 11; k++) g2[k] = pack2(G[k], G[k]);

    const int H = W;
    const float2* P;
    switch (scale) {
        case 1:  P = g_p1; break;
        case 2:  P = g_p2; break;
        default: P = g_p3; break;
    }

    const int tx    = blockIdx.x * TW;
    const int ty    = blockIdx.y * TH;
    const int plane = blockIdx.z;
    const size_t pbase = (size_t)plane * (size_t)W * (size_t)H;
    const int tid = threadIdx.x;

    // ---- stage 1: load tile + halo as interleaved (s,d) ----
    if (scale == 0) {
        for (int i = tid; i < IH * LW4; i += NT) {
            int r = i / LW4;
            int s = i - r * LW4;
            int gy = ty + r - 5;
            int gx = tx + 4 * s - 8;
            float4 a = make_float4(0.f, 0.f, 0.f, 0.f);
            float4 b = a;
            if ((unsigned)gy < (unsigned)H && (unsigned)gx <= (unsigned)(W - 4)) {
                size_t idx = pbase + (size_t)gy * W + gx;
                a = *reinterpret_cast<const float4*>(A0 + idx);
                b = *reinterpret_cast<const float4*>(B0 + idx);
            }
            float4 lo = make_float4(a.x + b.x, a.x - b.x, a.y + b.y, a.y - b.y);
            float4 hi = make_float4(a.z + b.z, a.z - b.z, a.w + b.w, a.w - b.w);
            *reinterpret_cast<float4*>(&sSD[r][4 * s])     = lo;
            *reinterpret_cast<float4*>(&sSD[r][4 * s + 2]) = hi;
        }
    } else {
        for (int i = tid; i < IH * NF4; i += NT) {
            int r = i / NF4;
            int s = i - r * NF4;
            int gy = ty + r - 5;
            int gx = tx + 2 * s - 8;
            float4 v = make_float4(0.f, 0.f, 0.f, 0.f);
            if ((unsigned)gy < (unsigned)H && (unsigned)gx <= (unsigned)(W - 2)) {
                v = *reinterpret_cast<const float4*>(P + pbase + (size_t)gy * W + gx);
            }
            *reinterpret_cast<float4*>(&sSD[r][2 * s]) = v;
        }
    }
    __syncthreads();

    // ---- fused 2x2 avg-pool for the next scale ((s,d) is linear) ----
    if (do_pool) {
        constexpr int PW = TW / 2, PH = TH / 2;
        float2* PD = (scale == 0) ? g_p1 : (scale == 1) ? g_p2 : g_p3;
        int pW = W >> 1;
        for (int i = tid; i < PW * PH; i += NT) {
            int pr = i / PW;
            int pc = i - pr * PW;
            int r = 5 + 2 * pr;
            int c = 8 + 2 * pc;
            float2 q00 = sSD[r][c],     q01 = sSD[r][c + 1];
            float2 q10 = sSD[r + 1][c], q11 = sSD[r + 1][c + 1];
            float2 o;
            o.x = 0.25f * (q00.x + q01.x + q10.x + q11.x);
            o.y = 0.25f * (q00.y + q01.y + q10.y + q11.y);
            size_t pidx = (size_t)plane * pW * pW
                        + (size_t)((ty >> 1) + pr) * pW + ((tx >> 1) + pc);
            PD[pidx] = o;
        }
    }

    // ---- stage 2: horizontal 11-tap pass, 8 outputs/thread-group ----
    // thread map row-fastest: consecutive lanes -> consecutive rows, so
    // 8-lane LDS phases rotate across bank-quads (pitch 400B) -> conflict-free.
    for (int i = tid; i < IH * SLOTS; i += NT) {
        int r  = i % IH;
        int sl = i / IH;
        int c0 = 8 * sl;
        ull w[20];   // cols c0+2 .. c0+21
        #pragma unroll
        for (int q = 0; q < 10; q++) {
            ulonglong2 u = *reinterpret_cast<const ulonglong2*>(&sSD[r][c0 + 2 + 2 * q]);
            w[2 * q]     = u.x;
            w[2 * q + 1] = u.y;
        }
        ull a1[8], a2[8];
        #pragma unroll
        for (int j = 0; j < 8; j++) { a1[j] = 0ull; a2[j] = 0ull; }
        #pragma unroll
        for (int m = 0; m < 18; m++) {   // output j, tap k: m = j+k, col c0+3+m = w[m+1]
            ull v  = w[m + 1];
            ull v2 = fmul2(v, v);
            #pragma unroll
            for (int j = 0; j < 8; j++) {
                int k = m - j;
                if (k >= 0 && k < 11) {
                    ffma2(a1[j], v,  g2[k]);
                    ffma2(a2[j], v2, g2[k]);
                }
            }
        }
        #pragma unroll
        for (int j = 0; j < 8; j++) {
            h12[r][c0 + j] = make_ulonglong2(a1[j], a2[j]);
        }
    }
    __syncthreads();

    // ---- stage 3: vertical 11-tap pass (f32x2), SSIM map, reduce ----
    float acc = 0.0f;
    {
        const int c  = tid % TW;
        const int r0 = (tid / TW) * RPT;
        ull s1[RPT], s2[RPT];
        #pragma unroll
        for (int j = 0; j < RPT; j++) { s1[j] = 0ull; s2[j] = 0ull; }
        #pragma unroll
        for (int t = 0; t < RPT + 10; t++) {
            ulonglong2 v = h12[r0 + t][c];
            #pragma unroll
            for (int j = 0; j < RPT; j++) {
                int k = t - j;
                if (k >= 0 && k < 11) {
                    ffma2(s1[j], v.x, g2[k]);
                    ffma2(s2[j], v.y, g2[k]);
                }
            }
        }
        const float C1 = 1e-4f;
        const float C2 = 9e-4f;
        #pragma unroll
        for (int j = 0; j < RPT; j++) {
            float mus, mud, es2, ed2;
            unpack2(s1[j], mus, mud);
            unpack2(s2[j], es2, ed2);
            float Aq = mus * mus;
            float Bq = mud * mud;
            float mu12  = 0.25f * (Aq - Bq);            // mu1*mu2
            float musq  = 0.5f  * (Aq + Bq);            // mu1^2+mu2^2
            float sigs  = 0.5f  * (es2 + ed2) - musq;   // sig1^2+sig2^2
            float sig12 = 0.25f * (es2 - ed2) - mu12;   // sig12
            float num = (2.0f * mu12 + C1) * (2.0f * sig12 + C2);
            float den = (musq + C1) * (sigs + C2);
            acc += __fdividef(num, den);
        }
    }

    // ---- block reduction -> one atomic per block ----
    #pragma unroll
    for (int o = 16; o > 0; o >>= 1)
        acc += __shfl_down_sync(0xffffffffu, acc, o);
    if ((tid & 31) == 0) red[tid >> 5] = acc;
    __syncthreads();
    if (tid == 0) {
        float s = 0.f;
        #pragma unroll
        for (int w = 0; w < NT / 32; w++) s += red[w];
        atomicAdd(&g_acc[scale], s);
    }
}

__global__ void finalize_kernel(float* __restrict__ out) {
    const float w[4] = {0.0448f, 0.2856f, 0.3001f, 0.2363f};
    float loss = 0.0f;
    float cnt = 48.0f * 512.0f * 512.0f;
    #pragma unroll
    for (int s = 0; s < 4; s++) {
        loss += w[s] * (1.0f - g_acc[s] / cnt);
        cnt *= 0.25f;
    }
    out[0] = loss;
    #pragma unroll
    for (int s = 0; s < 4; s++) g_acc[s] = 0.0f;   // reset for next replay
}

extern "C" void kernel_launch(void* const* d_in, const int* in_sizes, int n_in,
                              void* d_out, int out_size) {
    const float* img1 = (const float*)d_in[0];
    const float* img2 = (const float*)d_in[1];
    float* out = (float*)d_out;

    // scale 0: 512x512, 32x32 tiles, 128 thr (RPT=8)
    ssim_kernel<32, 32, 8><<<dim3(16, 16, NPLANES), 128>>>(img1, img2, 0, 512, 1);
    // scale 1: 256x256
    ssim_kernel<32, 32, 8><<<dim3(8, 8, NPLANES), 128>>>(nullptr, nullptr, 1, 256, 1);
    // scale 2: 128x128, 32x16 tiles (RPT=4)
    ssim_kernel<32, 16, 4><<<dim3(4, 8, NPLANES), 128>>>(nullptr, nullptr, 2, 128, 1);
    // scale 3: 64x64, 16x16 tiles (RPT=2)
    ssim_kernel<16, 16, 2><<<dim3(4, 4, NPLANES), 128>>>(nullptr, nullptr, 3, 64, 0);

    finalize_kernel<<<1, 1>>>(out);
}